// round 3
// baseline (speedup 1.0000x reference)
#include <cuda_runtime.h>
#include <cstdint>

#define ZDIM   128
#define MDIM   8192
#define NB     128
#define MT     64                    // M rows per CTA
#define NCTA   (MDIM / MT)           // 128 CTAs
#define KT     32                    // K per tile (128B rows)
#define NITER  (MDIM / KT)           // 256
#define STAGES 8
#define DEPTH  4
#define BT_BYTES   (MT * 128)        // 8 KB
#define ET_BYTES   (NB * 128)        // 16 KB
#define STG_BYTES  (BT_BYTES + ET_BYTES)      // 24 KB
#define RING_BYTES (STAGES * STG_BYTES)       // 192 KB
#define FULL_OFF   RING_BYTES
#define EMPTY_OFF  (RING_BYTES + 64)
#define SS_OFF     (RING_BYTES + 128)
#define SMEM_DYN   (RING_BYTES + 512 + 1024)
#define OUT_PLANE  (NB * MDIM)

__device__ float g_eps[OUT_PLANE];   // tf32-rounded eps scratch (4 MB)

static __device__ __forceinline__ uint32_t smem_u32(const void* p) {
    uint32_t a;
    asm("{ .reg .u64 t; cvta.to.shared.u64 t, %1; cvt.u32.u64 %0, t; }" : "=r"(a) : "l"(p));
    return a;
}

#define MBAR_INIT(a, c)  asm volatile("mbarrier.init.shared.b64 [%0], %1;" :: "r"((uint32_t)(a)), "r"((uint32_t)(c)) : "memory")
#define MBAR_ARRIVE(a)   asm volatile("mbarrier.arrive.shared.b64 _, [%0];" :: "r"((uint32_t)(a)) : "memory")

#define MBAR_WAIT(a, ph) do {                                                      \
    uint32_t _m = (uint32_t)(a), _p = (uint32_t)(ph);                              \
    asm volatile("{\n\t.reg .pred P;\n\t"                                          \
        "WL_%=:\n\t"                                                               \
        "mbarrier.try_wait.parity.acquire.cta.shared::cta.b64 P, [%0], %1, 0x989680;\n\t" \
        "@P bra.uni WD_%=;\n\t"                                                    \
        "bra.uni WL_%=;\n\t"                                                       \
        "WD_%=:\n\t}" :: "r"(_m), "r"(_p) : "memory");                             \
} while (0)

#define CP_ASYNC16(dst, src) \
    asm volatile("cp.async.cg.shared.global [%0], [%1], 16;" :: "r"((uint32_t)(dst)), "l"(src) : "memory")

#define LDS32(v, a) asm volatile("ld.shared.b32 %0, [%1];" : "=r"(v) : "r"(a))

#define MMA_TF32(d, a, b0, b1) \
    asm volatile("mma.sync.aligned.m16n8k8.row.col.f32.tf32.tf32.f32 " \
        "{%0,%1,%2,%3}, {%4,%5,%6,%7}, {%8,%9}, {%0,%1,%2,%3};" \
        : "+f"((d)[0]), "+f"((d)[1]), "+f"((d)[2]), "+f"((d)[3]) \
        : "r"((a)[0]), "r"((a)[1]), "r"((a)[2]), "r"((a)[3]), "r"(b0), "r"(b1))

// ---------------------------------------------------------------------------
// Fill kernel: mu / logvar planes + tf32-rounded eps scratch
// ---------------------------------------------------------------------------
__global__ void cov_fill(const float* __restrict__ mu, const float* __restrict__ logstd,
                         const float* __restrict__ eps, float* __restrict__ out) {
    int i = blockIdx.x * blockDim.x + threadIdx.x;
    if (i < OUT_PLANE) {
        int z = i & (ZDIM - 1);
        out[i] = mu[z];
        out[OUT_PLANE + i] = 2.0f * logstd[z];
        uint32_t r;
        asm("cvt.rna.tf32.f32 %0, %1;" : "=r"(r) : "f"(eps[i]));
        g_eps[i] = __uint_as_float(r);
    }
}

// ---------------------------------------------------------------------------
// Main kernel: 128 CTAs x 192 threads.
// warps 0-3: compute (two (1x2) pairs, K-split by tile parity); warps 4-5: producers.
// ---------------------------------------------------------------------------
__global__ void __launch_bounds__(192, 1) cov_main(
    const float* __restrict__ B, const float* __restrict__ mu,
    const float* __restrict__ logstd, float* __restrict__ out)
{
    extern __shared__ char smem_raw[];
    const uint32_t raw  = smem_u32(smem_raw);
    const uint32_t base = (raw + 1023u) & ~1023u;
    char* basep = smem_raw + (base - raw);
    float* ssp   = (float*)(basep + SS_OFF);
    float* smemC = (float*)basep;            // reused after main loop

    const int tid  = threadIdx.x;
    const int wid  = tid >> 5;
    const int lane = tid & 31;

    if (tid == 0) {
        #pragma unroll
        for (int s = 0; s < STAGES; s++) {
            MBAR_INIT(base + FULL_OFF  + s * 8, 64);  // 64 producer threads
            MBAR_INIT(base + EMPTY_OFF + s * 8, 2);   // lane0 of the 2 pair warps
        }
    }
    if (tid < MT) ssp[tid] = 0.0f;
    __syncthreads();

    if (wid < 4) {
        // ============== compute warps ==============
        const int pair = wid >> 1;               // tile parity owned
        const int nh   = wid & 1;                // n half (64 cols)
        const int g    = lane >> 2;              // 0..7
        const int tg   = lane & 3;               // 0..3
        const uint32_t swz = (uint32_t)g << 4;

        uint32_t xoff[4][2];
        #pragma unroll
        for (int sk = 0; sk < 4; sk++)
            #pragma unroll
            for (int hi = 0; hi < 2; hi++)
                xoff[sk][hi] = ((uint32_t)(32 * sk + tg * 4 + 16 * hi)) ^ swz;

        float C[4][8][4];
        #pragma unroll
        for (int q = 0; q < 4; q++)
            #pragma unroll
            for (int j = 0; j < 8; j++)
                #pragma unroll
                for (int e = 0; e < 4; e++) C[q][j][e] = 0.0f;
        float ss[8];
        #pragma unroll
        for (int sl = 0; sl < 8; sl++) ss[sl] = 0.0f;

        for (int it = pair; it < NITER; it += 2) {
            const int s  = it & (STAGES - 1);
            const int ph = (it >> 3) & 1;
            MBAR_WAIT(base + FULL_OFF + s * 8, ph);
            const uint32_t stg = base + (uint32_t)s * STG_BYTES;

            #pragma unroll
            for (int sk = 0; sk < 4; sk++) {
                uint32_t a[4][4];
                #pragma unroll
                for (int q = 0; q < 4; q++) {
                    uint32_t r0 = stg + (uint32_t)(16 * q + g) * 128u;
                    uint32_t r1 = r0 + 1024u;
                    LDS32(a[q][0], r0 + xoff[sk][0]);
                    LDS32(a[q][1], r1 + xoff[sk][0]);
                    LDS32(a[q][2], r0 + xoff[sk][1]);
                    LDS32(a[q][3], r1 + xoff[sk][1]);
                    // truncate to tf32 (matches what HMMA consumes) + fused sumsq
                    #pragma unroll
                    for (int e = 0; e < 4; e++) {
                        a[q][e] &= 0xFFFFE000u;
                        float f = __uint_as_float(a[q][e]);
                        ss[2 * q + (e & 1)] = fmaf(f, f, ss[2 * q + (e & 1)]);
                    }
                }
                #pragma unroll
                for (int j = 0; j < 8; j++) {
                    uint32_t er = stg + (uint32_t)BT_BYTES + (uint32_t)(nh * 64 + 8 * j + g) * 128u;
                    uint32_t b0, b1;
                    LDS32(b0, er + xoff[sk][0]);
                    LDS32(b1, er + xoff[sk][1]);
                    #pragma unroll
                    for (int q = 0; q < 4; q++) MMA_TF32(C[q][j], a[q], b0, b1);
                }
            }
            __syncwarp();
            if (lane == 0) MBAR_ARRIVE(base + EMPTY_OFF + s * 8);
        }

        // sumsq reduce (each element seen by both nh warps; count nh==0 only)
        if (nh == 0) {
            #pragma unroll
            for (int sl = 0; sl < 8; sl++) {
                float v = ss[sl];
                v += __shfl_xor_sync(0xffffffffu, v, 1);
                v += __shfl_xor_sync(0xffffffffu, v, 2);
                if (tg == 0) atomicAdd(&ssp[g + 8 * (sl & 1) + 16 * (sl >> 1)], v);
            }
        }
    } else {
        // ============== producer warps (64 threads) ==============
        const int p  = tid - 128;                // 0..63
        const int c  = p & 7;                    // 16B chunk in 128B row
        const int r0 = p >> 3;                   // 0..7
        const uint32_t dsw = ((uint32_t)(c * 16)) ^ ((uint32_t)r0 << 4);
        const float* gB = B + (size_t)blockIdx.x * MT * MDIM;

        int s = 0, ph = 1, fs = 0;
        for (int it = 0; it < NITER; it++) {
            MBAR_WAIT(base + EMPTY_OFF + s * 8, ph);
            const uint32_t stg = base + (uint32_t)s * STG_BYTES;
            const float* srcB = gB + it * KT + c * 4;
            #pragma unroll
            for (int u = 0; u < 8; u++) {
                int row = r0 + 8 * u;
                CP_ASYNC16(stg + (uint32_t)row * 128u + dsw, srcB + (size_t)row * MDIM);
            }
            const float* srcE = g_eps + it * KT + c * 4;
            #pragma unroll
            for (int u = 0; u < 16; u++) {
                int row = r0 + 8 * u;
                CP_ASYNC16(stg + (uint32_t)BT_BYTES + (uint32_t)row * 128u + dsw,
                           srcE + (size_t)row * MDIM);
            }
            asm volatile("cp.async.commit_group;" ::: "memory");
            if (it >= DEPTH - 1) {
                asm volatile("cp.async.wait_group %0;" :: "n"(DEPTH - 1) : "memory");
                MBAR_ARRIVE(base + FULL_OFF + fs * 8);
                if (++fs == STAGES) fs = 0;
            }
            if (++s == STAGES) { s = 0; ph ^= 1; }
        }
        asm volatile("cp.async.wait_group 0;" ::: "memory");
        #pragma unroll
        for (int d = 0; d < DEPTH - 1; d++) {
            MBAR_ARRIVE(base + FULL_OFF + fs * 8);
            if (++fs == STAGES) fs = 0;
        }
    }

    __syncthreads();

    // ============== epilogue: merge pair C's, scale, write ==============
    {
        const int nh = wid & 1;
        const int g  = lane >> 2;
        const int tg = lane & 3;
        if (wid < 4) {
            // recompute layout locals (same regs still live in wid<4 branch scope)
        }
        // pair A stores
        if (wid < 2) {
            const int nhh = wid & 1;
            // C still in registers: re-emit store loop. (Registers from branch above
            // remain live because this is the same function scope per warp.)
        }
    }
    // NOTE: the C-merge must reference the C registers, so do it inside one block:
    // (second pass, structured with explicit barriers executed by ALL threads)
    // -- handled below --
    goto epilogue;
epilogue:
    ;
    // Store pass 1: warps 0,1 write C into smemC[b*64+m]
    if (wid < 2) {
        const int nh = wid & 1, g = lane >> 2, tg = lane & 3;
        extern __shared__ char sraw2[];
        (void)sraw2;
        // C registers are out of scope here -- so this approach is invalid.
    }
    __syncthreads();
    __syncthreads();
    if (tid < 128) {
        int m = tid & 63, bh = tid >> 6;
        int mg = blockIdx.x * MT + m, z = mg & (ZDIM - 1);
        float sc  = rsqrtf(ssp[m]) * expf(logstd[z]);
        float muv = mu[z];
        float* op = out + 2 * (size_t)OUT_PLANE + mg;
        for (int b = bh * 64; b < bh * 64 + 64; b++)
            op[(size_t)b * MDIM] = fmaf(sc, smemC[b * 64 + m], muv);
    }
}

// ---- The structure above has a scoping bug (C regs out of scope for the merge).
// ---- Correct, compile-clean version of cov_main is below; it supersedes the one above.

__global__ void __launch_bounds__(192, 1) cov_main2(
    const float* __restrict__ B, const float* __restrict__ mu,
    const float* __restrict__ logstd, float* __restrict__ out)
{
    extern __shared__ char smem_raw[];
    const uint32_t raw  = smem_u32(smem_raw);
    const uint32_t base = (raw + 1023u) & ~1023u;
    char* basep = smem_raw + (base - raw);
    float* ssp   = (float*)(basep + SS_OFF);
    float* smemC = (float*)basep;

    const int tid  = threadIdx.x;
    const int wid  = tid >> 5;
    const int lane = tid & 31;

    if (tid == 0) {
        #pragma unroll
        for (int s = 0; s < STAGES; s++) {
            MBAR_INIT(base + FULL_OFF  + s * 8, 64);
            MBAR_INIT(base + EMPTY_OFF + s * 8, 2);
        }
    }
    if (tid < MT) ssp[tid] = 0.0f;
    __syncthreads();

    float C[4][8][4];
    const int pair = wid >> 1;
    const int nh   = wid & 1;
    const int g    = lane >> 2;
    const int tg   = lane & 3;

    if (wid < 4) {
        const uint32_t swz = (uint32_t)g << 4;
        uint32_t xoff[4][2];
        #pragma unroll
        for (int sk = 0; sk < 4; sk++)
            #pragma unroll
            for (int hi = 0; hi < 2; hi++)
                xoff[sk][hi] = ((uint32_t)(32 * sk + tg * 4 + 16 * hi)) ^ swz;

        #pragma unroll
        for (int q = 0; q < 4; q++)
            #pragma unroll
            for (int j = 0; j < 8; j++)
                #pragma unroll
                for (int e = 0; e < 4; e++) C[q][j][e] = 0.0f;
        float ss[8];
        #pragma unroll
        for (int sl = 0; sl < 8; sl++) ss[sl] = 0.0f;

        for (int it = pair; it < NITER; it += 2) {
            const int s  = it & (STAGES - 1);
            const int ph = (it >> 3) & 1;
            MBAR_WAIT(base + FULL_OFF + s * 8, ph);
            const uint32_t stg = base + (uint32_t)s * STG_BYTES;

            #pragma unroll
            for (int sk = 0; sk < 4; sk++) {
                uint32_t a[4][4];
                #pragma unroll
                for (int q = 0; q < 4; q++) {
                    uint32_t r0 = stg + (uint32_t)(16 * q + g) * 128u;
                    uint32_t r1 = r0 + 1024u;
                    LDS32(a[q][0], r0 + xoff[sk][0]);
                    LDS32(a[q][1], r1 + xoff[sk][0]);
                    LDS32(a[q][2], r0 + xoff[sk][1]);
                    LDS32(a[q][3], r1 + xoff[sk][1]);
                    #pragma unroll
                    for (int e = 0; e < 4; e++) {
                        a[q][e] &= 0xFFFFE000u;
                        float f = __uint_as_float(a[q][e]);
                        ss[2 * q + (e & 1)] = fmaf(f, f, ss[2 * q + (e & 1)]);
                    }
                }
                #pragma unroll
                for (int j = 0; j < 8; j++) {
                    uint32_t er = stg + (uint32_t)BT_BYTES + (uint32_t)(nh * 64 + 8 * j + g) * 128u;
                    uint32_t b0, b1;
                    LDS32(b0, er + xoff[sk][0]);
                    LDS32(b1, er + xoff[sk][1]);
                    #pragma unroll
                    for (int q = 0; q < 4; q++) MMA_TF32(C[q][j], a[q], b0, b1);
                }
            }
            __syncwarp();
            if (lane == 0) MBAR_ARRIVE(base + EMPTY_OFF + s * 8);
        }

        if (nh == 0) {
            #pragma unroll
            for (int sl = 0; sl < 8; sl++) {
                float v = ss[sl];
                v += __shfl_xor_sync(0xffffffffu, v, 1);
                v += __shfl_xor_sync(0xffffffffu, v, 2);
                if (tg == 0) atomicAdd(&ssp[g + 8 * (sl & 1) + 16 * (sl >> 1)], v);
            }
        }
    } else {
        const int p  = tid - 128;
        const int c  = p & 7;
        const int r0 = p >> 3;
        const uint32_t dsw = ((uint32_t)(c * 16)) ^ ((uint32_t)r0 << 4);
        const float* gB = B + (size_t)blockIdx.x * MT * MDIM;

        int s = 0, ph = 1, fs = 0;
        for (int it = 0; it < NITER; it++) {
            MBAR_WAIT(base + EMPTY_OFF + s * 8, ph);
            const uint32_t stg = base + (uint32_t)s * STG_BYTES;
            const float* srcB = gB + it * KT + c * 4;
            #pragma unroll
            for (int u = 0; u < 8; u++) {
                int row = r0 + 8 * u;
                CP_ASYNC16(stg + (uint32_t)row * 128u + dsw, srcB + (size_t)row * MDIM);
            }
            const float* srcE = g_eps + it * KT + c * 4;
            #pragma unroll
            for (int u = 0; u < 16; u++) {
                int row = r0 + 8 * u;
                CP_ASYNC16(stg + (uint32_t)BT_BYTES + (uint32_t)row * 128u + dsw,
                           srcE + (size_t)row * MDIM);
            }
            asm volatile("cp.async.commit_group;" ::: "memory");
            if (it >= DEPTH - 1) {
                asm volatile("cp.async.wait_group %0;" :: "n"(DEPTH - 1) : "memory");
                MBAR_ARRIVE(base + FULL_OFF + fs * 8);
                if (++fs == STAGES) fs = 0;
            }
            if (++s == STAGES) { s = 0; ph ^= 1; }
        }
        asm volatile("cp.async.wait_group 0;" ::: "memory");
        #pragma unroll
        for (int d = 0; d < DEPTH - 1; d++) {
            MBAR_ARRIVE(base + FULL_OFF + fs * 8);
            if (++fs == STAGES) fs = 0;
        }
    }

    __syncthreads();                 // all main-loop smem use done; ring reusable

    // pair A (warps 0,1) stores its C into smemC[b*64 + m]
    if (wid < 2) {
        #pragma unroll
        for (int q = 0; q < 4; q++)
            #pragma unroll
            for (int j = 0; j < 8; j++) {
                int col = nh * 64 + 8 * j + 2 * tg;
                int row = 16 * q + g;
                smemC[(col    ) * 64 + row    ] = C[q][j][0];
                smemC[(col + 1) * 64 + row    ] = C[q][j][1];
                smemC[(col    ) * 64 + row + 8] = C[q][j][2];
                smemC[(col + 1) * 64 + row + 8] = C[q][j][3];
            }
    }
    __syncthreads();
    // pair B (warps 2,3) accumulates
    if (wid >= 2 && wid < 4) {
        #pragma unroll
        for (int q = 0; q < 4; q++)
            #pragma unroll
            for (int j = 0; j < 8; j++) {
                int col = nh * 64 + 8 * j + 2 * tg;
                int row = 16 * q + g;
                smemC[(col    ) * 64 + row    ] += C[q][j][0];
                smemC[(col + 1) * 64 + row    ] += C[q][j][1];
                smemC[(col    ) * 64 + row + 8] += C[q][j][2];
                smemC[(col + 1) * 64 + row + 8] += C[q][j][3];
            }
    }
    __syncthreads();

    if (tid < 128) {
        int m = tid & 63, bh = tid >> 6;
        int mg = blockIdx.x * MT + m, z = mg & (ZDIM - 1);
        float sc  = rsqrtf(ssp[m]) * expf(logstd[z]);
        float muv = mu[z];
        float* op = out + 2 * (size_t)OUT_PLANE + mg;
        #pragma unroll 4
        for (int b = bh * 64; b < bh * 64 + 64; b++)
            op[(size_t)b * MDIM] = fmaf(sc, smemC[b * 64 + m], muv);
    }
}

extern "C" void kernel_launch(void* const* d_in, const int* in_sizes, int n_in,
                              void* d_out, int out_size) {
    const float* mu     = (const float*)d_in[0];
    const float* logstd = (const float*)d_in[1];
    const float* B      = (const float*)d_in[2];
    const float* eps    = (const float*)d_in[3];
    float* out = (float*)d_out;

    cudaFuncSetAttribute(cov_main2, cudaFuncAttributeMaxDynamicSharedMemorySize, SMEM_DYN);

    cov_fill<<<(OUT_PLANE + 511) / 512, 512>>>(mu, logstd, eps, out);
    cov_main2<<<NCTA, 192, SMEM_DYN>>>(B, mu, logstd, out);
}

// round 4
// speedup vs baseline: 1.1167x; 1.1167x over previous
#include <cuda_runtime.h>
#include <cstdint>

#define ZDIM   128
#define MDIM   8192
#define NB     128
#define MT     64                    // M rows per CTA
#define NCTA   (MDIM / MT)           // 128 CTAs
#define KT     32                    // K per tile (128B rows)
#define NITER  (MDIM / KT)           // 256
#define STAGES 8
#define DEPTH  4
#define BT_BYTES   (MT * 128)        // 8 KB
#define ET_BYTES   (NB * 128)        // 16 KB
#define STG_BYTES  (BT_BYTES + ET_BYTES)      // 24 KB
#define RING_BYTES (STAGES * STG_BYTES)       // 192 KB
#define FULL_OFF   RING_BYTES
#define EMPTY_OFF  (RING_BYTES + 64)
#define SS_OFF     (RING_BYTES + 128)
#define SMEM_DYN   (RING_BYTES + 1536)
#define OUT_PLANE  (NB * MDIM)

__device__ float g_eps[OUT_PLANE];   // tf32-rounded eps scratch (4 MB)

static __device__ __forceinline__ uint32_t smem_u32(const void* p) {
    uint32_t a;
    asm("{ .reg .u64 t; cvta.to.shared.u64 t, %1; cvt.u32.u64 %0, t; }" : "=r"(a) : "l"(p));
    return a;
}

#define MBAR_INIT(a, c)  asm volatile("mbarrier.init.shared.b64 [%0], %1;" :: "r"((uint32_t)(a)), "r"((uint32_t)(c)) : "memory")
#define MBAR_ARRIVE(a)   asm volatile("mbarrier.arrive.shared.b64 _, [%0];" :: "r"((uint32_t)(a)) : "memory")

#define MBAR_WAIT(a, ph) do {                                                      \
    uint32_t _m = (uint32_t)(a), _p = (uint32_t)(ph);                              \
    asm volatile("{\n\t.reg .pred P;\n\t"                                          \
        "WL_%=:\n\t"                                                               \
        "mbarrier.try_wait.parity.acquire.cta.shared::cta.b64 P, [%0], %1, 0x989680;\n\t" \
        "@P bra.uni WD_%=;\n\t"                                                    \
        "bra.uni WL_%=;\n\t"                                                       \
        "WD_%=:\n\t}" :: "r"(_m), "r"(_p) : "memory");                             \
} while (0)

#define CP_ASYNC16(dst, src) \
    asm volatile("cp.async.cg.shared.global [%0], [%1], 16;" :: "r"((uint32_t)(dst)), "l"(src) : "memory")

#define LDSM_X4(r, addr) \
    asm volatile("ldmatrix.sync.aligned.m8n8.x4.shared.b16 {%0,%1,%2,%3}, [%4];" \
        : "=r"((r)[0]), "=r"((r)[1]), "=r"((r)[2]), "=r"((r)[3]) : "r"((uint32_t)(addr)))

#define MMA_TF32(d, a, b0, b1) \
    asm volatile("mma.sync.aligned.m16n8k8.row.col.f32.tf32.tf32.f32 " \
        "{%0,%1,%2,%3}, {%4,%5,%6,%7}, {%8,%9}, {%0,%1,%2,%3};" \
        : "+f"((d)[0]), "+f"((d)[1]), "+f"((d)[2]), "+f"((d)[3]) \
        : "r"((a)[0]), "r"((a)[1]), "r"((a)[2]), "r"((a)[3]), "r"(b0), "r"(b1))

// ---------------------------------------------------------------------------
__global__ void cov_fill(const float* __restrict__ mu, const float* __restrict__ logstd,
                         const float* __restrict__ eps, float* __restrict__ out) {
    int i = blockIdx.x * blockDim.x + threadIdx.x;
    if (i < OUT_PLANE) {
        int z = i & (ZDIM - 1);
        out[i] = mu[z];
        out[OUT_PLANE + i] = 2.0f * logstd[z];
        uint32_t r;
        asm("cvt.rna.tf32.f32 %0, %1;" : "=r"(r) : "f"(eps[i]));
        g_eps[i] = __uint_as_float(r);
    }
}

// ---------------------------------------------------------------------------
// 128 CTAs x 384 threads.
// warps 0-7: compute, warp = (kpar = wid>>2) x (mq = (wid>>1)&1) x (nh = wid&1)
//   each computes M32 x N64, K-split 2-way by tile parity. C = 64 regs.
// warps 8-11: producers (128 threads, cp.async pipeline).
// ---------------------------------------------------------------------------
__global__ void __launch_bounds__(384, 1) cov_main(
    const float* __restrict__ B, const float* __restrict__ mu,
    const float* __restrict__ logstd, float* __restrict__ out)
{
    extern __shared__ char smem_raw[];
    const uint32_t raw  = smem_u32(smem_raw);
    const uint32_t base = (raw + 1023u) & ~1023u;
    char* basep = smem_raw + (base - raw);
    float* ssp   = (float*)(basep + SS_OFF);
    float* smemC = (float*)basep;              // reused after main loop (32 KB)

    const int tid  = threadIdx.x;
    const int wid  = tid >> 5;
    const int lane = tid & 31;

    if (tid == 0) {
        #pragma unroll
        for (int s = 0; s < STAGES; s++) {
            MBAR_INIT(base + FULL_OFF  + s * 8, 128);  // 128 producer threads
            MBAR_INIT(base + EMPTY_OFF + s * 8, 4);    // lane0 of 4 consumer warps
        }
    }
    if (tid < MT) ssp[tid] = 0.0f;
    __syncthreads();

    float C[2][8][4];
    const int kpar = wid >> 2;
    const int mq   = (wid >> 1) & 1;
    const int nh   = wid & 1;
    const int g    = lane >> 2;
    const int tg   = lane & 3;

    if (wid < 8) {
        // ---------------- compute warps ----------------
        // per-lane LDSM source rows/cols (swizzle baked in)
        const uint32_t rowA = (uint32_t)((lane & 7) + 8 * ((lane >> 3) & 1));
        const uint32_t rowB = (uint32_t)((lane & 7) + 8 * (lane >> 4));
        const uint32_t swzl = (uint32_t)(lane & 7) << 4;
        uint32_t colA[4], colB[4];
        #pragma unroll
        for (int sk = 0; sk < 4; sk++) {
            colA[sk] = ((uint32_t)(sk * 32 + 16 * (lane >> 4))) ^ swzl;
            colB[sk] = ((uint32_t)(sk * 32 + 16 * ((lane >> 3) & 1))) ^ swzl;
        }
        // A row base offsets for q = 0,1 ; B row base offsets for jp = 0..3
        uint32_t aRow[2], bRow[4];
        #pragma unroll
        for (int q = 0; q < 2; q++)
            aRow[q] = ((uint32_t)(mq * 32 + q * 16) + rowA) * 128u;
        #pragma unroll
        for (int jp = 0; jp < 4; jp++)
            bRow[jp] = (uint32_t)BT_BYTES + ((uint32_t)(nh * 64 + jp * 16) + rowB) * 128u;

        #pragma unroll
        for (int q = 0; q < 2; q++)
            #pragma unroll
            for (int j = 0; j < 8; j++)
                #pragma unroll
                for (int e = 0; e < 4; e++) C[q][j][e] = 0.0f;
        float ss[4];
        ss[0] = ss[1] = ss[2] = ss[3] = 0.0f;

        for (int it = kpar; it < NITER; it += 2) {
            const int s  = it & (STAGES - 1);
            const int ph = (it >> 3) & 1;
            MBAR_WAIT(base + FULL_OFF + s * 8, ph);
            const uint32_t stg = base + (uint32_t)s * STG_BYTES;

            #pragma unroll
            for (int sk = 0; sk < 4; sk++) {
                uint32_t a[2][4];
                #pragma unroll
                for (int q = 0; q < 2; q++)
                    LDSM_X4(a[q], stg + aRow[q] + colA[sk]);
                uint32_t b[4][4];
                #pragma unroll
                for (int jp = 0; jp < 4; jp++)
                    LDSM_X4(b[jp], stg + bRow[jp] + colB[sk]);

                if (nh == 0) {
                    #pragma unroll
                    for (int q = 0; q < 2; q++)
                        #pragma unroll
                        for (int e = 0; e < 4; e++) {
                            float f = __uint_as_float(a[q][e] & 0xFFFFE000u);
                            ss[q * 2 + (e & 1)] = fmaf(f, f, ss[q * 2 + (e & 1)]);
                        }
                }
                #pragma unroll
                for (int jp = 0; jp < 4; jp++)
                    #pragma unroll
                    for (int q = 0; q < 2; q++) {
                        MMA_TF32(C[q][jp * 2 + 0], a[q], b[jp][0], b[jp][1]);
                        MMA_TF32(C[q][jp * 2 + 1], a[q], b[jp][2], b[jp][3]);
                    }
            }
            __syncwarp();
            if (lane == 0) MBAR_ARRIVE(base + EMPTY_OFF + s * 8);
        }

        if (nh == 0) {
            #pragma unroll
            for (int sl = 0; sl < 4; sl++) {     // sl = q*2 + h  (h: row g vs g+8)
                float v = ss[sl];
                v += __shfl_xor_sync(0xffffffffu, v, 1);
                v += __shfl_xor_sync(0xffffffffu, v, 2);
                if (tg == 0)
                    atomicAdd(&ssp[mq * 32 + (sl >> 1) * 16 + (sl & 1) * 8 + g], v);
            }
        }
    } else {
        // ---------------- producer warps (128 threads) ----------------
        const int p = tid - 256;                 // 0..127
        const int c = p & 7;                     // 16B chunk within 128B row
        const int r = p >> 3;                    // 0..15
        const uint32_t dsw = ((uint32_t)(c * 16)) ^ ((uint32_t)(r & 7) << 4);
        const float* gB = B + (size_t)blockIdx.x * MT * MDIM;

        int s = 0, ph = 1, fs = 0;
        for (int it = 0; it < NITER; it++) {
            MBAR_WAIT(base + EMPTY_OFF + s * 8, ph);
            const uint32_t stg = base + (uint32_t)s * STG_BYTES;
            const float* srcB = gB + it * KT + c * 4;
            #pragma unroll
            for (int u = 0; u < 4; u++) {
                int row = r + 16 * u;
                CP_ASYNC16(stg + (uint32_t)row * 128u + dsw, srcB + (size_t)row * MDIM);
            }
            const float* srcE = g_eps + it * KT + c * 4;
            #pragma unroll
            for (int u = 0; u < 8; u++) {
                int row = r + 16 * u;
                CP_ASYNC16(stg + (uint32_t)BT_BYTES + (uint32_t)row * 128u + dsw,
                           srcE + (size_t)row * MDIM);
            }
            asm volatile("cp.async.commit_group;" ::: "memory");
            if (it >= DEPTH - 1) {
                asm volatile("cp.async.wait_group %0;" :: "n"(DEPTH - 1) : "memory");
                MBAR_ARRIVE(base + FULL_OFF + fs * 8);
                if (++fs == STAGES) fs = 0;
            }
            if (++s == STAGES) { s = 0; ph ^= 1; }
        }
        asm volatile("cp.async.wait_group 0;" ::: "memory");
        #pragma unroll
        for (int d = 0; d < DEPTH - 1; d++) {
            MBAR_ARRIVE(base + FULL_OFF + fs * 8);
            if (++fs == STAGES) fs = 0;
        }
    }

    __syncthreads();                 // main-loop smem use done; ring reusable

    // kpar 0 warps store C into smemC[col*64 + row]
    if (wid < 4) {
        #pragma unroll
        for (int q = 0; q < 2; q++)
            #pragma unroll
            for (int j = 0; j < 8; j++) {
                int col = nh * 64 + j * 8 + 2 * tg;
                int row = mq * 32 + q * 16 + g;
                smemC[(col    ) * 64 + row    ] = C[q][j][0];
                smemC[(col + 1) * 64 + row    ] = C[q][j][1];
                smemC[(col    ) * 64 + row + 8] = C[q][j][2];
                smemC[(col + 1) * 64 + row + 8] = C[q][j][3];
            }
    }
    __syncthreads();
    // kpar 1 warps accumulate
    if (wid >= 4 && wid < 8) {
        #pragma unroll
        for (int q = 0; q < 2; q++)
            #pragma unroll
            for (int j = 0; j < 8; j++) {
                int col = nh * 64 + j * 8 + 2 * tg;
                int row = mq * 32 + q * 16 + g;
                smemC[(col    ) * 64 + row    ] += C[q][j][0];
                smemC[(col + 1) * 64 + row    ] += C[q][j][1];
                smemC[(col    ) * 64 + row + 8] += C[q][j][2];
                smemC[(col + 1) * 64 + row + 8] += C[q][j][3];
            }
    }
    __syncthreads();

    if (tid < 128) {
        int m = tid & 63, bh = tid >> 6;
        int mg = blockIdx.x * MT + m, z = mg & (ZDIM - 1);
        float sc  = rsqrtf(ssp[m]) * expf(logstd[z]);
        float muv = mu[z];
        float* op = out + 2 * (size_t)OUT_PLANE + mg;
        #pragma unroll 4
        for (int b = bh * 64; b < bh * 64 + 64; b++)
            op[(size_t)b * MDIM] = fmaf(sc, smemC[b * 64 + m], muv);
    }
}

extern "C" void kernel_launch(void* const* d_in, const int* in_sizes, int n_in,
                              void* d_out, int out_size) {
    const float* mu     = (const float*)d_in[0];
    const float* logstd = (const float*)d_in[1];
    const float* B      = (const float*)d_in[2];
    const float* eps    = (const float*)d_in[3];
    float* out = (float*)d_out;

    cudaFuncSetAttribute(cov_main, cudaFuncAttributeMaxDynamicSharedMemorySize, SMEM_DYN);

    cov_fill<<<(OUT_PLANE + 511) / 512, 512>>>(mu, logstd, eps, out);
    cov_main<<<NCTA, 384, SMEM_DYN>>>(B, mu, logstd, out);
}